// round 1
// baseline (speedup 1.0000x reference)
#include <cuda_runtime.h>
#include <cuda_bf16.h>
#include <cstdint>

#define N_SAMP   262144
#define ZD       2
#define CTX      128
#define HID      128
#define TEMB     32
#define NSTEPS   50
#define SPB      64      // samples per block
#define WARPS    8

// output layout: traj [51,N,2] | us [50,N,2] | times [51]
#define US_OFF    ((long long)(NSTEPS+1) * N_SAMP * ZD)
#define TAIL_OFF  (US_OFF + (long long)NSTEPS * N_SAMP * ZD)

// per-step precomputed constants
__device__ float g_twd[NSTEPS * HID];
__device__ float g_twc[NSTEPS * HID];
__device__ float g_dts[NSTEPS];
__device__ float g_coef[NSTEPS];

typedef unsigned long long u64;

__device__ __forceinline__ float fsilu(float x) {
    float e = __expf(-x);
    return __fdividef(x, 1.0f + e);
}
__device__ __forceinline__ u64 f2pack(float a, float b) {
    u64 r; asm("mov.b64 %0, {%1, %2};" : "=l"(r) : "f"(a), "f"(b)); return r;
}
__device__ __forceinline__ void f2unpack(u64 v, float& a, float& b) {
    asm("mov.b64 {%0, %1}, %2;" : "=f"(a), "=f"(b) : "l"(v));
}
__device__ __forceinline__ u64 ffma2(u64 a, u64 b, u64 c) {
    u64 d; asm("fma.rn.f32x2 %0, %1, %2, %3;" : "=l"(d) : "l"(a), "l"(b), "l"(c)); return d;
}
__device__ __forceinline__ u64 lds_u64(uint32_t addr) {
    u64 v; asm volatile("ld.shared.b64 %0, [%1];" : "=l"(v) : "r"(addr)); return v;
}

// ---------------------------------------------------------------------------
// Kernel A: per-step constants (temb @ W1_temb + b1, dt, diffusion coef) + times tail
// ---------------------------------------------------------------------------
__global__ void prep_kernel(const float* __restrict__ times,
                            const float* __restrict__ freqs,
                            const float* __restrict__ dW1, const float* __restrict__ db1,
                            const float* __restrict__ cW1, const float* __restrict__ cb1,
                            const float* __restrict__ log_diff,
                            float* __restrict__ out)
{
    __shared__ float temb[TEMB];
    int tid = threadIdx.x;  // 128 threads
    if (tid < NSTEPS + 1) out[TAIL_OFF + tid] = times[tid];
    float gb = log1pf(__expf(log_diff[0]));  // softplus
    for (int i = 0; i < NSTEPS; i++) {
        float t = times[i];
        __syncthreads();
        if (tid < TEMB / 2) {
            float a = 6.2831853071795864f * t * freqs[tid];
            temb[tid]            = sinf(a);
            temb[tid + TEMB / 2] = cosf(a);
        }
        __syncthreads();
        float ad = db1[tid], ac = cb1[tid];
#pragma unroll 8
        for (int m = 0; m < TEMB; m++) {
            float tv = temb[m];
            ad += tv * dW1[(ZD + CTX + m) * HID + tid];
            ac += tv * cW1[(ZD + CTX + m) * HID + tid];
        }
        g_twd[i * HID + tid] = ad;
        g_twc[i * HID + tid] = ac;
        if (tid == 0) {
            float dt = times[i + 1] - t;
            g_dts[i]  = dt;
            g_coef[i] = gb * (1.0f - t) * sqrtf(fmaxf(dt, 1e-12f));
        }
    }
}

// ---------------------------------------------------------------------------
// Kernel B: persistent 50-step SDE. Each CTA = 64 samples, 8 warps (8 samples/warp).
// SMEM: baseD(32K) baseC(32K) W2d(64K) W2c(64K) a1buf(16K) = 208KB, 1 CTA/SM.
// ---------------------------------------------------------------------------
__device__ __forceinline__ void compute_base(float* __restrict__ dst,
                                             const float* __restrict__ tmp,
                                             const float* __restrict__ W1,
                                             int w, int l)
{
    // each warp computes base rows for its own 8 samples
    float acc[8][4];
#pragma unroll
    for (int s8 = 0; s8 < 8; s8++)
#pragma unroll
        for (int c = 0; c < 4; c++) acc[s8][c] = 0.f;
#pragma unroll 2
    for (int r = 0; r < CTX; r++) {
        float w1v[4];
#pragma unroll
        for (int c = 0; c < 4; c++) w1v[c] = W1[(ZD + r) * HID + l + 32 * c];
#pragma unroll
        for (int s8 = 0; s8 < 8; s8++) {
            float a = tmp[(w * 8 + s8) * HID + r];
#pragma unroll
            for (int c = 0; c < 4; c++) acc[s8][c] += a * w1v[c];
        }
    }
#pragma unroll
    for (int s8 = 0; s8 < 8; s8++)
#pragma unroll
        for (int c = 0; c < 4; c++)
            dst[(w * 8 + s8) * HID + l + 32 * c] = acc[s8][c];
}

__global__ void __launch_bounds__(256, 1)
sde_kernel(const float* __restrict__ z0,
           const float* __restrict__ pctx, const float* __restrict__ cctx,
           const float* __restrict__ noise,
           const float* __restrict__ dW1, const float* __restrict__ dW2,
           const float* __restrict__ db2, const float* __restrict__ dW3,
           const float* __restrict__ db3,
           const float* __restrict__ cW1, const float* __restrict__ cW2,
           const float* __restrict__ cb2, const float* __restrict__ cW3,
           const float* __restrict__ cb3,
           float* __restrict__ out)
{
    extern __shared__ float sm[];
    float* baseD = sm;                       // 64*128
    float* baseC = baseD + SPB * HID;        // 64*128
    float* sW2d  = baseC + SPB * HID;        // 128*128
    float* sW2c  = sW2d + HID * HID;         // 128*128
    u64*   a1buf = (u64*)(sW2c + HID * HID); // 8*4*64 u64

    int tid = threadIdx.x;
    int w = tid >> 5, l = tid & 31;
    int blockBase = blockIdx.x * SPB;
    int sbase = blockBase + w * 8;

    // ---- phase 1: base = ctx @ W1[2:130] (both MLPs), stage W2 into SMEM ----
    float* tmp = sW2d;  // temporary ctx tile
    for (int idx = tid; idx < SPB * HID; idx += 256) tmp[idx] = pctx[(long long)blockBase * HID + idx];
    __syncthreads();
    compute_base(baseD, tmp, dW1, w, l);
    __syncthreads();
    for (int idx = tid; idx < SPB * HID; idx += 256) tmp[idx] = cctx[(long long)blockBase * HID + idx];
    __syncthreads();
    compute_base(baseC, tmp, cW1, w, l);
    __syncthreads();
    for (int idx = tid; idx < HID * HID; idx += 256) { sW2d[idx] = dW2[idx]; sW2c[idx] = cW2[idx]; }
    __syncthreads();

    // ---- per-lane constant weights in registers ----
    float wz[2][2][4], w3r[2][4][2], b2r[2][4];
#pragma unroll
    for (int c = 0; c < 4; c++) {
        int j = l + 32 * c;
        wz[0][0][c] = dW1[0 * HID + j];  wz[0][1][c] = dW1[1 * HID + j];
        wz[1][0][c] = cW1[0 * HID + j];  wz[1][1][c] = cW1[1 * HID + j];
        w3r[0][c][0] = dW3[j * ZD + 0];  w3r[0][c][1] = dW3[j * ZD + 1];
        w3r[1][c][0] = cW3[j * ZD + 0];  w3r[1][c][1] = cW3[j * ZD + 1];
        b2r[0][c] = db2[j];              b2r[1][c] = cb2[j];
    }
    int myS = l >> 1, myD = l & 1;
    float b3d_own = myD ? db3[1] : db3[0];
    float b3c_own = myD ? cb3[1] : cb3[0];

    // ---- init z (owner lanes l<16 hold (s = l>>1, d = l&1)) and write traj[0] ----
    float z_own = 0.f;
    if (l < 16) {
        long long gs = sbase + myS;
        z_own = z0[gs * ZD + myD];
        out[gs * ZD + myD] = z_own;  // traj[0]
    }
    float zz[8][2];
#pragma unroll
    for (int s = 0; s < 8; s++) {
        zz[s][0] = __shfl_sync(0xffffffffu, z_own, 2 * s);
        zz[s][1] = __shfl_sync(0xffffffffu, z_own, 2 * s + 1);
    }

    uint32_t myA = (uint32_t)__cvta_generic_to_shared(a1buf + w * 256);

    // ---- 50-step loop, fully warp-local ----
    for (int i = 0; i < NSTEPS; i++) {
        float up[8][2], fq[8][2];
#pragma unroll
        for (int s = 0; s < 8; s++) { up[s][0] = up[s][1] = 0.f; fq[s][0] = fq[s][1] = 0.f; }

#pragma unroll
        for (int m = 0; m < 2; m++) {
            const float* bs  = m ? baseC : baseD;
            const float* sW2 = m ? sW2c  : sW2d;
            const float* tw  = (m ? g_twc : g_twd) + i * HID;
            u64 acc[4][4];
#pragma unroll
            for (int p = 0; p < 4; p++)
#pragma unroll
                for (int c = 0; c < 4; c++) acc[p][c] = 0ull;

#pragma unroll
            for (int ch = 0; ch < 2; ch++) {
                __syncwarp();
                // layer 1 (rank-2 update) + silu -> packed sample-pairs in a1buf
#pragma unroll
                for (int p = 0; p < 4; p++) {
#pragma unroll
                    for (int t = 0; t < 2; t++) {
                        int kk = l + 32 * t;
                        int k  = ch * 64 + kk;
                        int c  = ch * 2 + t;
                        float twv = tw[k];
                        int s0 = w * 8 + 2 * p;
                        float h0 = bs[s0 * HID + k] + twv
                                 + zz[2 * p][0]     * wz[m][0][c] + zz[2 * p][1]     * wz[m][1][c];
                        float h1 = bs[(s0 + 1) * HID + k] + twv
                                 + zz[2 * p + 1][0] * wz[m][0][c] + zz[2 * p + 1][1] * wz[m][1][c];
                        a1buf[w * 256 + p * 64 + kk] = f2pack(fsilu(h0), fsilu(h1));
                    }
                }
                __syncwarp();
                // layer 2: packed fp32x2 GEMM (8 samples x 128 j over 64 k)
#pragma unroll 4
                for (int kk = 0; kk < 64; kk++) {
                    int k = ch * 64 + kk;
                    u64 A[4];
#pragma unroll
                    for (int p = 0; p < 4; p++) A[p] = lds_u64(myA + (p * 64 + kk) * 8);
                    u64 B[4];
#pragma unroll
                    for (int c = 0; c < 4; c++) {
                        float wv = sW2[k * HID + l + 32 * c];
                        B[c] = f2pack(wv, wv);
                    }
#pragma unroll
                    for (int p = 0; p < 4; p++)
#pragma unroll
                        for (int c = 0; c < 4; c++)
                            acc[p][c] = ffma2(A[p], B[c], acc[p][c]);
                }
            }
            // epilogue: silu(h2 + b2), layer-3 partials
#pragma unroll
            for (int p = 0; p < 4; p++) {
#pragma unroll
                for (int c = 0; c < 4; c++) {
                    float lo, hi;
                    f2unpack(acc[p][c], lo, hi);
                    lo = fsilu(lo + b2r[m][c]);
                    hi = fsilu(hi + b2r[m][c]);
                    if (m == 0) {
                        up[2 * p][0]     += lo * w3r[0][c][0]; up[2 * p][1]     += lo * w3r[0][c][1];
                        up[2 * p + 1][0] += hi * w3r[0][c][0]; up[2 * p + 1][1] += hi * w3r[0][c][1];
                    } else {
                        fq[2 * p][0]     += lo * w3r[1][c][0]; fq[2 * p][1]     += lo * w3r[1][c][1];
                        fq[2 * p + 1][0] += hi * w3r[1][c][0]; fq[2 * p + 1][1] += hi * w3r[1][c][1];
                    }
                }
            }
        }

        // ---- cross-lane reduction (32 independent 5-stage butterflies) ----
        float rv[32];
#pragma unroll
        for (int s = 0; s < 8; s++) {
#pragma unroll
            for (int d = 0; d < 2; d++) {
                rv[s * 2 + d]      = up[s][d];
                rv[16 + s * 2 + d] = fq[s][d];
            }
        }
#pragma unroll
        for (int st = 0; st < 5; st++) {
            int off = 16 >> st;
#pragma unroll
            for (int j = 0; j < 32; j++) rv[j] += __shfl_xor_sync(0xffffffffu, rv[j], off);
        }

        float dt = g_dts[i], cf = g_coef[i];
        if (l < 16) {
            float uv = 0.f, fv = 0.f;
#pragma unroll
            for (int j = 0; j < 16; j++) {
                if (l == j) { uv = rv[j]; fv = rv[16 + j]; }
            }
            uv += b3d_own;
            fv += b3c_own;
            long long gs = sbase + myS;
            long long io = (long long)i * N_SAMP;
            out[US_OFF + (io + gs) * 2 + myD] = uv;
            float xi = noise[(io + gs) * 2 + myD];
            z_own = z_own + (uv + fv) * dt + xi * cf;
            out[(long long)(i + 1) * N_SAMP * 2 + gs * 2 + myD] = z_own;
        }
#pragma unroll
        for (int s = 0; s < 8; s++) {
            zz[s][0] = __shfl_sync(0xffffffffu, z_own, 2 * s);
            zz[s][1] = __shfl_sync(0xffffffffu, z_own, 2 * s + 1);
        }
    }
}

// ---------------------------------------------------------------------------
extern "C" void kernel_launch(void* const* d_in, const int* in_sizes, int n_in,
                              void* d_out, int out_size)
{
    const float* z0       = (const float*)d_in[0];
    const float* pctx     = (const float*)d_in[1];
    const float* cctx     = (const float*)d_in[2];
    const float* times    = (const float*)d_in[3];
    const float* noise    = (const float*)d_in[4];
    const float* freqs    = (const float*)d_in[5];
    const float* dW1      = (const float*)d_in[6];
    const float* db1      = (const float*)d_in[7];
    const float* dW2      = (const float*)d_in[8];
    const float* db2      = (const float*)d_in[9];
    const float* dW3      = (const float*)d_in[10];
    const float* db3      = (const float*)d_in[11];
    const float* cW1      = (const float*)d_in[12];
    const float* cb1      = (const float*)d_in[13];
    const float* cW2      = (const float*)d_in[14];
    const float* cb2      = (const float*)d_in[15];
    const float* cW3      = (const float*)d_in[16];
    const float* cb3      = (const float*)d_in[17];
    const float* log_diff = (const float*)d_in[18];
    float* out = (float*)d_out;

    const int smemB = (SPB * HID * 2 + HID * HID * 2) * 4 + WARPS * 4 * 64 * 8; // 212992
    cudaFuncSetAttribute(sde_kernel, cudaFuncAttributeMaxDynamicSharedMemorySize, smemB);

    prep_kernel<<<1, 128>>>(times, freqs, dW1, db1, cW1, cb1, log_diff, out);
    sde_kernel<<<N_SAMP / SPB, 256, smemB>>>(z0, pctx, cctx, noise,
                                             dW1, dW2, db2, dW3, db3,
                                             cW1, cW2, cb2, cW3, cb3, out);
}

// round 2
// speedup vs baseline: 1.1977x; 1.1977x over previous
#include <cuda_runtime.h>
#include <cuda_bf16.h>
#include <cstdint>

#define N_SAMP   262144
#define ZD       2
#define CTX      128
#define HID      128
#define TEMB     32
#define NSTEPS   50
#define SPB      64      // samples per block
#define NWARPS   16      // 8 diffusion-MLP warps + 8 cnf-MLP warps

// output layout: traj [51,N,2] | us [50,N,2] | times [51]
#define US_OFF    ((long long)(NSTEPS+1) * N_SAMP * ZD)
#define TAIL_OFF  (US_OFF + (long long)NSTEPS * N_SAMP * ZD)

// per-step precomputed constants
__device__ float g_twd[NSTEPS * HID];
__device__ float g_twc[NSTEPS * HID];
__device__ float g_dts[NSTEPS];
__device__ float g_coef[NSTEPS];

typedef unsigned long long u64;

__device__ __forceinline__ float fsilu(float x) {
    float e = __expf(-x);
    return __fdividef(x, 1.0f + e);
}
__device__ __forceinline__ u64 f2pack(float a, float b) {
    u64 r; asm("mov.b64 %0, {%1, %2};" : "=l"(r) : "f"(a), "f"(b)); return r;
}
__device__ __forceinline__ void f2unpack(u64 v, float& a, float& b) {
    asm("mov.b64 {%0, %1}, %2;" : "=f"(a), "=f"(b) : "l"(v));
}
__device__ __forceinline__ u64 ffma2(u64 a, u64 b, u64 c) {
    u64 d; asm("fma.rn.f32x2 %0, %1, %2, %3;" : "=l"(d) : "l"(a), "l"(b), "l"(c)); return d;
}
__device__ __forceinline__ u64 lds_u64(uint32_t addr) {
    u64 v; asm volatile("ld.shared.b64 %0, [%1];" : "=l"(v) : "r"(addr)); return v;
}

// ---------------------------------------------------------------------------
// Kernel A: per-step constants (temb @ W1_temb + b1, dt, diffusion coef) + times tail
// ---------------------------------------------------------------------------
__global__ void prep_kernel(const float* __restrict__ times,
                            const float* __restrict__ freqs,
                            const float* __restrict__ dW1, const float* __restrict__ db1,
                            const float* __restrict__ cW1, const float* __restrict__ cb1,
                            const float* __restrict__ log_diff,
                            float* __restrict__ out)
{
    __shared__ float temb[TEMB];
    int tid = threadIdx.x;  // 128 threads
    if (tid < NSTEPS + 1) out[TAIL_OFF + tid] = times[tid];
    float gb = log1pf(__expf(log_diff[0]));  // softplus
    for (int i = 0; i < NSTEPS; i++) {
        float t = times[i];
        __syncthreads();
        if (tid < TEMB / 2) {
            float a = 6.2831853071795864f * t * freqs[tid];
            temb[tid]            = sinf(a);
            temb[tid + TEMB / 2] = cosf(a);
        }
        __syncthreads();
        float ad = db1[tid], ac = cb1[tid];
#pragma unroll 8
        for (int m = 0; m < TEMB; m++) {
            float tv = temb[m];
            ad += tv * dW1[(ZD + CTX + m) * HID + tid];
            ac += tv * cW1[(ZD + CTX + m) * HID + tid];
        }
        g_twd[i * HID + tid] = ad;
        g_twc[i * HID + tid] = ac;
        if (tid == 0) {
            float dt = times[i + 1] - t;
            g_dts[i]  = dt;
            g_coef[i] = gb * (1.0f - t) * sqrtf(fmaxf(dt, 1e-12f));
        }
    }
}

// ---------------------------------------------------------------------------
// base = ctx @ W1[2:130] for one warp's 8 samples
// ---------------------------------------------------------------------------
__device__ __forceinline__ void compute_base(float* __restrict__ dst,
                                             const float* __restrict__ tmp,
                                             const float* __restrict__ W1,
                                             int wg, int l)
{
    float acc[8][4];
#pragma unroll
    for (int s8 = 0; s8 < 8; s8++)
#pragma unroll
        for (int c = 0; c < 4; c++) acc[s8][c] = 0.f;
#pragma unroll 2
    for (int r = 0; r < CTX; r++) {
        float w1v[4];
#pragma unroll
        for (int c = 0; c < 4; c++) w1v[c] = W1[(ZD + r) * HID + l + 32 * c];
#pragma unroll
        for (int s8 = 0; s8 < 8; s8++) {
            float a = tmp[(wg * 8 + s8) * HID + r];
#pragma unroll
            for (int c = 0; c < 4; c++) acc[s8][c] += a * w1v[c];
        }
    }
#pragma unroll
    for (int s8 = 0; s8 < 8; s8++)
#pragma unroll
        for (int c = 0; c < 4; c++)
            dst[(wg * 8 + s8) * HID + l + 32 * c] = acc[s8][c];
}

// ---------------------------------------------------------------------------
// Kernel B: persistent 50-step SDE. 512 threads / CTA, 64 samples.
// Warps 0-7: diffusion MLP (u), warps 8-15: cnf MLP (f). 8 samples per warp.
// SMEM: baseD(32K) baseC(32K) W2d(64K) W2c(64K) a1buf(32K) uf(2K) = 231424B.
// ---------------------------------------------------------------------------
__global__ void __launch_bounds__(512, 1)
sde_kernel(const float* __restrict__ z0,
           const float* __restrict__ pctx, const float* __restrict__ cctx,
           const float* __restrict__ noise,
           const float* __restrict__ dW1, const float* __restrict__ dW2,
           const float* __restrict__ db2, const float* __restrict__ dW3,
           const float* __restrict__ db3,
           const float* __restrict__ cW1, const float* __restrict__ cW2,
           const float* __restrict__ cb2, const float* __restrict__ cW3,
           const float* __restrict__ cb3,
           float* __restrict__ out)
{
    extern __shared__ float sm[];
    float* baseD = sm;                       // 64*128
    float* baseC = baseD + SPB * HID;        // 64*128
    float* sW2d  = baseC + SPB * HID;        // 128*128
    float* sW2c  = sW2d + HID * HID;         // 128*128
    u64*   a1buf = (u64*)(sW2c + HID * HID); // 16 warps * 256 u64
    float* uf    = (float*)(a1buf + NWARPS * 256); // 2 bufs * 2 mlp * 64 * 2

    int tid = threadIdx.x;
    int w = tid >> 5, l = tid & 31;
    int m  = w >> 3;      // 0 = diffusion MLP (u), 1 = cnf MLP (f)
    int wg = w & 7;       // sample group
    int blockBase = blockIdx.x * SPB;
    int sbase = blockBase + wg * 8;
    int myS = l >> 1, myD = l & 1;

    const float* W1 = m ? cW1 : dW1;

    // ---- phase 1: stage ctx tiles into W2 areas, compute base, then load W2 ----
    for (int idx = tid; idx < SPB * HID; idx += 512) {
        sW2d[idx] = pctx[(long long)blockBase * HID + idx];
        sW2c[idx] = cctx[(long long)blockBase * HID + idx];
    }
    __syncthreads();
    {
        const float* tmp = m ? sW2c : sW2d;
        float* dstBase   = m ? baseC : baseD;
        compute_base(dstBase, tmp, W1, wg, l);
    }
    __syncthreads();
    for (int idx = tid; idx < HID * HID; idx += 512) { sW2d[idx] = dW2[idx]; sW2c[idx] = cW2[idx]; }
    __syncthreads();

    // ---- per-lane constant weights in registers (single MLP) ----
    const float* W2s   = m ? sW2c : sW2d;
    const float* W3    = m ? cW3  : dW3;
    const float* b2    = m ? cb2  : db2;
    const float* b3    = m ? cb3  : db3;
    const float* twAll = m ? g_twc : g_twd;
    const float* bsw   = (m ? baseC : baseD) + wg * 8 * HID;

    float wzr[2][4], w3r[4][2], b2r[4];
#pragma unroll
    for (int c = 0; c < 4; c++) {
        int j = l + 32 * c;
        wzr[0][c] = W1[0 * HID + j];
        wzr[1][c] = W1[1 * HID + j];
        w3r[c][0] = W3[j * ZD + 0];
        w3r[c][1] = W3[j * ZD + 1];
        b2r[c]    = b2[j];
    }
    float b3_own = b3[myD];

    // ---- init z (owner lanes l<16 hold (s = l>>1, d = l&1)); cnf warps write traj[0] ----
    float z_own = 0.f;
    if (l < 16) {
        long long gs = sbase + myS;
        z_own = z0[gs * ZD + myD];
        if (m) out[gs * ZD + myD] = z_own;  // traj[0]
    }
    float zz[8][2];
#pragma unroll
    for (int s = 0; s < 8; s++) {
        zz[s][0] = __shfl_sync(0xffffffffu, z_own, 2 * s);
        zz[s][1] = __shfl_sync(0xffffffffu, z_own, 2 * s + 1);
    }

    uint32_t myA = (uint32_t)__cvta_generic_to_shared(a1buf + w * 256);

    // ---- 50-step loop ----
    for (int i = 0; i < NSTEPS; i++) {
        float twr[4];
#pragma unroll
        for (int c = 0; c < 4; c++) twr[c] = twAll[i * HID + l + 32 * c];

        u64 acc[4][4];
#pragma unroll
        for (int p = 0; p < 4; p++)
#pragma unroll
            for (int c = 0; c < 4; c++) acc[p][c] = 0ull;

#pragma unroll
        for (int ch = 0; ch < 2; ch++) {
            __syncwarp();
            // layer 1 (rank-2 update) + silu -> packed sample-pairs in a1buf
#pragma unroll
            for (int p = 0; p < 4; p++) {
#pragma unroll
                for (int t = 0; t < 2; t++) {
                    int kk = l + 32 * t;
                    int k  = ch * 64 + kk;
                    int c  = ch * 2 + t;
                    float twv = twr[c];
                    int s0 = 2 * p;
                    float h0 = bsw[s0 * HID + k] + twv
                             + zz[2 * p][0]     * wzr[0][c] + zz[2 * p][1]     * wzr[1][c];
                    float h1 = bsw[(s0 + 1) * HID + k] + twv
                             + zz[2 * p + 1][0] * wzr[0][c] + zz[2 * p + 1][1] * wzr[1][c];
                    a1buf[w * 256 + p * 64 + kk] = f2pack(fsilu(h0), fsilu(h1));
                }
            }
            __syncwarp();
            // layer 2: packed fp32x2 GEMM (8 samples x 128 j over 64 k)
#pragma unroll 4
            for (int kk = 0; kk < 64; kk++) {
                int k = ch * 64 + kk;
                u64 A[4];
#pragma unroll
                for (int p = 0; p < 4; p++) A[p] = lds_u64(myA + (p * 64 + kk) * 8);
                u64 B[4];
#pragma unroll
                for (int c = 0; c < 4; c++) {
                    float wv = W2s[k * HID + l + 32 * c];
                    B[c] = f2pack(wv, wv);
                }
#pragma unroll
                for (int p = 0; p < 4; p++)
#pragma unroll
                    for (int c = 0; c < 4; c++)
                        acc[p][c] = ffma2(A[p], B[c], acc[p][c]);
            }
        }

        // epilogue: silu(h2 + b2), layer-3 partials
        float rv[16];
#pragma unroll
        for (int j = 0; j < 16; j++) rv[j] = 0.f;
#pragma unroll
        for (int p = 0; p < 4; p++) {
#pragma unroll
            for (int c = 0; c < 4; c++) {
                float lo, hi;
                f2unpack(acc[p][c], lo, hi);
                lo = fsilu(lo + b2r[c]);
                hi = fsilu(hi + b2r[c]);
                rv[(2 * p) * 2 + 0]     += lo * w3r[c][0];
                rv[(2 * p) * 2 + 1]     += lo * w3r[c][1];
                rv[(2 * p + 1) * 2 + 0] += hi * w3r[c][0];
                rv[(2 * p + 1) * 2 + 1] += hi * w3r[c][1];
            }
        }

        // ---- folding butterfly reduction: lane l ends with sum for j = l & 15 ----
#pragma unroll
        for (int j = 0; j < 16; j++) rv[j] += __shfl_xor_sync(0xffffffffu, rv[j], 16);
#pragma unroll
        for (int off = 8; off >= 1; off >>= 1) {
#pragma unroll
            for (int j = 0; j < off; j++) {
                float a = rv[j], b = rv[j + off];
                float mine  = (l & off) ? b : a;
                float other = (l & off) ? a : b;
                float recv  = __shfl_xor_sync(0xffffffffu, other, off);
                rv[j] = mine + recv;
            }
        }
        float myval = rv[0] + b3_own;  // valid for lanes l<16 as (myS, myD)

        // ---- cross-group exchange (double-buffered, one barrier per step) ----
        int bufo = (i & 1) * 256;
        if (l < 16) uf[bufo + m * 128 + (wg * 8 + myS) * 2 + myD] = myval;
        __syncthreads();

        float dt = g_dts[i], cf = g_coef[i];
        if (l < 16) {
            float ov = uf[bufo + (1 - m) * 128 + (wg * 8 + myS) * 2 + myD];
            long long gs = sbase + myS;
            long long io = (long long)i * N_SAMP;
            float xi = noise[(io + gs) * 2 + myD];
            z_own = z_own + (myval + ov) * dt + xi * cf;
            if (m == 0) out[US_OFF + (io + gs) * 2 + myD] = myval;  // u from diffusion warps
            else        out[(long long)(i + 1) * N_SAMP * 2 + gs * 2 + myD] = z_own;  // traj
        }
#pragma unroll
        for (int s = 0; s < 8; s++) {
            zz[s][0] = __shfl_sync(0xffffffffu, z_own, 2 * s);
            zz[s][1] = __shfl_sync(0xffffffffu, z_own, 2 * s + 1);
        }
    }
}

// ---------------------------------------------------------------------------
extern "C" void kernel_launch(void* const* d_in, const int* in_sizes, int n_in,
                              void* d_out, int out_size)
{
    const float* z0       = (const float*)d_in[0];
    const float* pctx     = (const float*)d_in[1];
    const float* cctx     = (const float*)d_in[2];
    const float* times    = (const float*)d_in[3];
    const float* noise    = (const float*)d_in[4];
    const float* freqs    = (const float*)d_in[5];
    const float* dW1      = (const float*)d_in[6];
    const float* db1      = (const float*)d_in[7];
    const float* dW2      = (const float*)d_in[8];
    const float* db2      = (const float*)d_in[9];
    const float* dW3      = (const float*)d_in[10];
    const float* db3      = (const float*)d_in[11];
    const float* cW1      = (const float*)d_in[12];
    const float* cb1      = (const float*)d_in[13];
    const float* cW2      = (const float*)d_in[14];
    const float* cb2      = (const float*)d_in[15];
    const float* cW3      = (const float*)d_in[16];
    const float* cb3      = (const float*)d_in[17];
    const float* log_diff = (const float*)d_in[18];
    float* out = (float*)d_out;

    const int smemB = (SPB * HID * 2 + HID * HID * 2) * 4  // base + W2
                    + NWARPS * 256 * 8                     // a1buf
                    + 2 * 2 * SPB * ZD * 4;                // uf exchange
    cudaFuncSetAttribute(sde_kernel, cudaFuncAttributeMaxDynamicSharedMemorySize, smemB);

    prep_kernel<<<1, 128>>>(times, freqs, dW1, db1, cW1, cb1, log_diff, out);
    sde_kernel<<<N_SAMP / SPB, 512, smemB>>>(z0, pctx, cctx, noise,
                                             dW1, dW2, db2, dW3, db3,
                                             cW1, cW2, cb2, cW3, cb3, out);
}